// round 14
// baseline (speedup 1.0000x reference)
#include <cuda_runtime.h>
#include <cuda_bf16.h>
#include <cstdint>

// Problem constants: B=2048, Z=64, A=8, H=512, T=64
#define BB   2048
#define ZZ   64
#define AA   8
#define HH   512
#define TT   64
#define N4H  2048

// GEMM tiling: one CTA per SM, uniform wave. 128x256 tile, 3 split pairs per chunk.
#define BM   128
#define BN   256
#define BK   32
#define NIT  16
#define LDS_ROW 40         // padded row (bf16): 32 data + 8 pad -> 80B, conflict-free ldmatrix

#define A_TILE_B 10240     // 128 rows x 80B
#define B_TILE_B 20480     // 256 rows x 80B
#define STAGE_B  61440     // hhi | hlo | whi | wlo
#define DYN_SMEM 122880

// ---------------- device scratch (no cudaMalloc allowed) ----------------
__device__ float          g_xproj[(size_t)BB * N4H];         // 16 MB, [b][col']
__device__ __nv_bfloat16  g_whi[(size_t)N4H * HH];           // 2 MB, permuted rows
__device__ __nv_bfloat16  g_wlo[(size_t)N4H * HH];           // 2 MB
__device__ float          g_c[(size_t)BB * HH];              // 4 MB
__device__ __nv_bfloat16  g_hhi[(size_t)TT * BB * HH];       // 128 MB, [t][b][k]
__device__ __nv_bfloat16  g_hlo[(size_t)TT * BB * HH];       // 128 MB

// ---------------- PTX helpers (all baseline: sm_80+) ----------------
__device__ __forceinline__ uint32_t smem_u32(const void* p) {
    uint32_t a;
    asm("{ .reg .u64 t; cvta.to.shared.u64 t, %1; cvt.u32.u64 %0, t; }" : "=r"(a) : "l"(p));
    return a;
}
__device__ __forceinline__ void ldsm4(uint32_t* r, uint32_t addr) {
    asm volatile("ldmatrix.sync.aligned.m8n8.x4.shared.b16 {%0,%1,%2,%3}, [%4];"
                 : "=r"(r[0]), "=r"(r[1]), "=r"(r[2]), "=r"(r[3]) : "r"(addr));
}
__device__ __forceinline__ void mma16816(float* d, const uint32_t* a, const uint32_t* b) {
    asm volatile("mma.sync.aligned.m16n8k16.row.col.f32.bf16.bf16.f32 "
                 "{%0,%1,%2,%3}, {%4,%5,%6,%7}, {%8,%9}, {%0,%1,%2,%3};"
                 : "+f"(d[0]), "+f"(d[1]), "+f"(d[2]), "+f"(d[3])
                 : "r"(a[0]), "r"(a[1]), "r"(a[2]), "r"(a[3]), "r"(b[0]), "r"(b[1]));
}
__device__ __forceinline__ void cpasync16(uint32_t saddr, const void* g) {
    asm volatile("cp.async.cg.shared.global [%0], [%1], 16;" :: "r"(saddr), "l"(g));
}
#define CP_COMMIT() asm volatile("cp.async.commit_group;")
#define CP_WAIT0()  asm volatile("cp.async.wait_group 0;")

__device__ __forceinline__ float sigm_f(float x) {
    x = fminf(fmaxf(x, -30.f), 30.f);
    return 1.f / (1.f + __expf(-x));
}
__device__ __forceinline__ float tanh_f(float x) {
    x = fminf(fmaxf(x, -15.f), 15.f);
    float e = __expf(2.f * x);
    return (e - 1.f) / (e + 1.f);
}

// ---------------- kernel: split+permute W_hh into bf16 hi/lo ----------------
__global__ void wsplit_kernel(const float* __restrict__ Whh) {
    int i = blockIdx.x * 256 + threadIdx.x;   // 2048*512 = 1M
    int j = i >> 9, k = i & 511;
    float w = Whh[i];
    int np = ((j & 511) << 2) + (j >> 9);     // gate-interleaved row: unit*4+gate
    __nv_bfloat16 hi = __float2bfloat16(w);
    g_whi[(size_t)np * HH + k] = hi;
    g_wlo[(size_t)np * HH + k] = __float2bfloat16(w - __bfloat162float(hi));
}

// ---------------- kernel: x_proj ([b][col'], gate-interleaved cols) ----------------
__global__ void xproj_kernel(const float* __restrict__ z,
                             const float* __restrict__ Wih,
                             const float* __restrict__ bih,
                             const float* __restrict__ bhh) {
    __shared__ float zs[16][68];
    __shared__ float ws[64][65];
    __shared__ float bs[64];
    int tid = threadIdx.x;
    int j0 = blockIdx.x * 64;
    int b0 = blockIdx.y * 16;

    for (int e = tid; e < 16 * 64; e += 256) {
        int r = e >> 6, c = e & 63;
        zs[r][c] = z[(b0 + r) * ZZ + c];
    }
    for (int e = tid; e < 64 * 64; e += 256) {
        int r = e >> 6, c = e & 63;
        ws[r][c] = Wih[(j0 + r) * (AA + ZZ) + AA + c];
    }
    if (tid < 64) bs[tid] = bih[j0 + tid] + bhh[j0 + tid];
    __syncthreads();

    int jl = tid & 63;
    int bq = tid >> 6;
    float acc[4];
#pragma unroll
    for (int bi = 0; bi < 4; bi++) acc[bi] = bs[jl];
#pragma unroll 8
    for (int k = 0; k < 64; k++) {
        float w = ws[jl][k];
#pragma unroll
        for (int bi = 0; bi < 4; bi++)
            acc[bi] = fmaf(zs[bq * 4 + bi][k], w, acc[bi]);
    }
    int jg = j0 + jl;
    int dest = ((jg & 511) << 2) + (jg >> 9);
#pragma unroll
    for (int bi = 0; bi < 4; bi++)
        g_xproj[(size_t)(b0 + bq * 4 + bi) * N4H + dest] = acc[bi];
}

// ---------------- step kernel: mma.sync split-bf16 GEMM + LSTM cell ----------------
// grid (8, 16): blockIdx.x = N tile (256 gate cols = 64 units), blockIdx.y = M tile (128 batch)
// One CTA per SM (128 CTAs, occ 1). Per chunk: acc += hhi*whi + hhi*wlo + hlo*whi.
// Stage: hhi(10240) | hlo(10240) | whi(20480) | wlo(20480); 2 stages; ONE sync per chunk.
__global__ __launch_bounds__(256, 1) void step_kernel(int t) {
    extern __shared__ __align__(16) char dsm[];

    const int tid = threadIdx.x, wid = tid >> 5, lid = tid & 31;
    const int warp_m = wid & 1, warp_n = wid >> 1;      // 2 x 4 warp grid, warp tile 64x64
    const int n0 = blockIdx.x * BN;
    const int b0 = blockIdx.y * BM;
    const uint32_t sb = smem_u32(dsm);

    float acc[4][8][4];
#pragma unroll
    for (int mf = 0; mf < 4; mf++)
#pragma unroll
        for (int nf = 0; nf < 8; nf++)
#pragma unroll
            for (int j = 0; j < 4; j++) acc[mf][nf][j] = 0.f;

    if (t > 0) {
        const int r4 = tid >> 2, c4 = tid & 3;          // rows 0..63, 16B-col 0..3

        auto load_chunk = [&](int kc, int s) {
            int kk = kc * BK;
            const __nv_bfloat16* hh = g_hhi + ((size_t)(t - 1) * BB + b0) * HH + kk;
            const __nv_bfloat16* hl = g_hlo + ((size_t)(t - 1) * BB + b0) * HH + kk;
            const __nv_bfloat16* bw = g_whi + (size_t)n0 * HH + kk;
            const __nv_bfloat16* bl = g_wlo + (size_t)n0 * HH + kk;
            uint32_t st = sb + s * STAGE_B;
#pragma unroll
            for (int rb = 0; rb < 2; rb++) {            // A tiles: 128 rows
                int r = r4 + rb * 64;
                uint32_t o = (r * LDS_ROW + c4 * 8) * 2;
                size_t gofs = (size_t)r * HH + c4 * 8;
                cpasync16(st + 0 * A_TILE_B + o, hh + gofs);
                cpasync16(st + 1 * A_TILE_B + o, hl + gofs);
            }
#pragma unroll
            for (int rb = 0; rb < 4; rb++) {            // B tiles: 256 rows
                int r = r4 + rb * 64;
                uint32_t o = (r * LDS_ROW + c4 * 8) * 2;
                size_t gofs = (size_t)r * HH + c4 * 8;
                cpasync16(st + 20480 + o, bw + gofs);   // whi at 2*A_TILE_B
                cpasync16(st + 40960 + o, bl + gofs);   // wlo at 2*A_TILE_B + B_TILE_B
            }
        };

        // per-lane ldmatrix address components
        const int sub = lid >> 3, lrow = lid & 7;
        const int rowA = warp_m * 64 + (sub & 1) * 8 + lrow;    // + mf*16
        const int kcA  = (sub >> 1);                            // + ks*2
        const int rowB = warp_n * 64 + (sub >> 1) * 8 + lrow;   // + np*16
        const int kcB  = (sub & 1);                             // + ks*2

        load_chunk(0, 0);
        CP_COMMIT();

        for (int it = 0; it < NIT; it++) {
            int s = it & 1;
            CP_WAIT0();                    // chunk it resident (this thread)
            __syncthreads();               // visible to all; stage s^1 free for reuse
            if (it + 1 < NIT) {
                load_chunk(it + 1, s ^ 1); // overlaps with compute below
                CP_COMMIT();
            }

            uint32_t hhb = sb + s * STAGE_B;
            uint32_t hlb = hhb + A_TILE_B;
            uint32_t bwb = hhb + 20480;
            uint32_t blb = hhb + 40960;
#pragma unroll
            for (int ks = 0; ks < 2; ks++) {
                uint32_t bfw[4][4], bfl[4][4];
#pragma unroll
                for (int np = 0; np < 4; np++) {
                    uint32_t off = ((rowB + np * 16) * LDS_ROW + (kcB + ks * 2) * 8) * 2;
                    ldsm4(bfw[np], bwb + off);
                    ldsm4(bfl[np], blb + off);
                }
                {   // h_hi x {W_hi, W_lo}
                    uint32_t afr[4][4];
#pragma unroll
                    for (int mf = 0; mf < 4; mf++)
                        ldsm4(afr[mf], hhb + ((rowA + mf * 16) * LDS_ROW + (kcA + ks * 2) * 8) * 2);
#pragma unroll
                    for (int mf = 0; mf < 4; mf++)
#pragma unroll
                        for (int nf = 0; nf < 8; nf++)
                            mma16816(acc[mf][nf], afr[mf], &bfw[nf >> 1][(nf & 1) * 2]);
#pragma unroll
                    for (int mf = 0; mf < 4; mf++)
#pragma unroll
                        for (int nf = 0; nf < 8; nf++)
                            mma16816(acc[mf][nf], afr[mf], &bfl[nf >> 1][(nf & 1) * 2]);
                }
                {   // h_lo x W_hi
                    uint32_t afr[4][4];
#pragma unroll
                    for (int mf = 0; mf < 4; mf++)
                        ldsm4(afr[mf], hlb + ((rowA + mf * 16) * LDS_ROW + (kcA + ks * 2) * 8) * 2);
#pragma unroll
                    for (int mf = 0; mf < 4; mf++)
#pragma unroll
                        for (int nf = 0; nf < 8; nf++)
                            mma16816(acc[mf][nf], afr[mf], &bfw[nf >> 1][(nf & 1) * 2]);
                }
            }
        }
        __syncthreads();                   // last compute done before epilogue smem reuse
    }

    // ---- epilogue: gates -> LSTM cell, stage h(hi/lo) + c, coalesced writeback ----
    float*          stc  = (float*)dsm;                        // [128][65] fp32
    __nv_bfloat16*  sthi = (__nv_bfloat16*)(dsm + 33280);      // [128][66]
    __nv_bfloat16*  stlo = (__nv_bfloat16*)(dsm + 50176);      // [128][66]
    const int u0 = n0 >> 2;                                    // 64 units per tile

    const int q = lid & 3, g = lid >> 2;
    const bool even = (q & 1) == 0;

#pragma unroll
    for (int mf = 0; mf < 4; mf++) {
#pragma unroll
        for (int half = 0; half < 2; half++) {
            int r = warp_m * 64 + mf * 16 + g + half * 8;      // local batch row
            int b = b0 + r;
#pragma unroll
            for (int nf = 0; nf < 8; nf++) {
                int col = n0 + warp_n * 64 + nf * 8 + q * 2;   // global gate col (even)
                float v0 = acc[mf][nf][half * 2 + 0];
                float v1 = acc[mf][nf][half * 2 + 1];
                float2 xp = *(const float2*)&g_xproj[(size_t)b * N4H + col];
                v0 += xp.x; v1 += xp.y;
                // lane q holds cols (q*2, q*2+1); partner q^1 holds the other gate pair
                float w0 = __shfl_xor_sync(0xffffffffu, v0, 1);
                float w1 = __shfl_xor_sync(0xffffffffu, v1, 1);
                if (even) {
                    // this lane: (i, f); partner: (g, o)
                    float iv = sigm_f(v0);
                    float fv = sigm_f(v1);
                    float gv = tanh_f(w0);
                    float ov = sigm_f(w1);
                    int u = col >> 2;                          // global hidden unit
                    float cold = (t > 0) ? g_c[(size_t)b * HH + u] : 0.f;
                    float cn = fmaf(fv, cold, iv * gv);
                    float hn = ov * tanh_f(cn);
                    __nv_bfloat16 hi = __float2bfloat16(hn);
                    int ul = u - u0;
                    stc[r * 65 + ul]  = cn;
                    sthi[r * 66 + ul] = hi;
                    stlo[r * 66 + ul] = __float2bfloat16(hn - __bfloat162float(hi));
                }
            }
        }
    }
    __syncthreads();

    const size_t hb = ((size_t)t * BB + b0) * HH + u0;
#pragma unroll 4
    for (int idx = tid; idx < BM * 64; idx += 256) {
        int r = idx >> 6, u = idx & 63;
        g_c[(size_t)(b0 + r) * HH + u0 + u] = stc[r * 65 + u];
        g_hhi[hb + (size_t)r * HH + u] = sthi[r * 66 + u];
        g_hlo[hb + (size_t)r * HH + u] = stlo[r * 66 + u];
    }
}

// ---------------- output projection: out[b][t][a] = (hi+lo) . W_out[a] + b_out ----------------
__global__ __launch_bounds__(256) void out_kernel(const float* __restrict__ Wo,
                                                  const float* __restrict__ bo,
                                                  float* __restrict__ out) {
    __shared__ float Ws[AA * HH];
    for (int e = threadIdx.x; e < AA * HH; e += 256) Ws[e] = Wo[e];
    __syncthreads();

    int id = blockIdx.x * 256 + threadIdx.x;          // 131072 rows
    int tt = id >> 11;                                // t (0..63)
    int b = id & (BB - 1);
    const __nv_bfloat16* ph = g_hhi + ((size_t)tt * BB + b) * HH;
    const __nv_bfloat16* pl = g_hlo + ((size_t)tt * BB + b) * HH;

    float acc[AA];
#pragma unroll
    for (int a = 0; a < AA; a++) acc[a] = 0.f;

    for (int k = 0; k < HH; k += 8) {
        uint4 vh = *(const uint4*)(ph + k);
        uint4 vl = *(const uint4*)(pl + k);
        const __nv_bfloat162* h2 = (const __nv_bfloat162*)&vh;
        const __nv_bfloat162* l2 = (const __nv_bfloat162*)&vl;
        float hv[8];
#pragma unroll
        for (int m = 0; m < 4; m++) {
            float2 fh = __bfloat1622float2(h2[m]);
            float2 fl = __bfloat1622float2(l2[m]);
            hv[2 * m + 0] = fh.x + fl.x;
            hv[2 * m + 1] = fh.y + fl.y;
        }
#pragma unroll
        for (int a = 0; a < AA; a++) {
#pragma unroll
            for (int m = 0; m < 8; m++)
                acc[a] = fmaf(hv[m], Ws[a * HH + k + m], acc[a]);
        }
    }
#pragma unroll
    for (int a = 0; a < AA; a++)
        out[((size_t)b * TT + tt) * AA + a] = acc[a] + bo[a];
}

// ---------------- launch ----------------
extern "C" void kernel_launch(void* const* d_in, const int* in_sizes, int n_in,
                              void* d_out, int out_size) {
    const float* z    = (const float*)d_in[0];
    const float* Wih  = (const float*)d_in[1];
    const float* Whh  = (const float*)d_in[2];
    const float* bih  = (const float*)d_in[3];
    const float* bhh  = (const float*)d_in[4];
    const float* Wout = (const float*)d_in[5];
    const float* bout = (const float*)d_in[6];
    float* out = (float*)d_out;

    cudaFuncSetAttribute(step_kernel, cudaFuncAttributeMaxDynamicSharedMemorySize, DYN_SMEM);

    wsplit_kernel<<<(N4H * HH) / 256, 256>>>(Whh);
    xproj_kernel<<<dim3(N4H / 64, BB / 16), 256>>>(z, Wih, bih, bhh);
    for (int t = 0; t < TT; t++)
        step_kernel<<<dim3(N4H / BN, BB / BM), 256, DYN_SMEM>>>(t);
    out_kernel<<<(BB * TT) / 256, 256>>>(Wout, bout, out);
}

// round 16
// speedup vs baseline: 1.3039x; 1.3039x over previous
#include <cuda_runtime.h>
#include <cuda_bf16.h>
#include <cstdint>

// Problem constants: B=2048, Z=64, A=8, H=512, T=64
#define BB   2048
#define ZZ   64
#define AA   8
#define HH   512
#define TT   64
#define N4H  2048

// GEMM tiling (R13-proven shape): 128x128 tile, occ 2, 3 split pairs per chunk
#define BM   128
#define BN   128
#define BK   32
#define NIT  16
#define LDS_ROW 40         // padded row (bf16): 32 data + 8 pad -> 80B, conflict-free ldmatrix

#define TILE_B   10240     // 128 rows x 80B
#define STAGE_B  40960     // hhi | hlo | whi | wlo
#define DYN_SMEM 81920

// ---------------- device scratch (no cudaMalloc allowed) ----------------
__device__ float          g_xproj[(size_t)BB * N4H];         // 16 MB, [b][col']
__device__ __nv_bfloat16  g_whi[(size_t)N4H * HH];           // 2 MB, permuted rows
__device__ __nv_bfloat16  g_wlo[(size_t)N4H * HH];           // 2 MB
__device__ float          g_c[(size_t)BB * HH];              // 4 MB
__device__ __nv_bfloat16  g_hhi[(size_t)TT * BB * HH];       // 128 MB, [t][b][k]
__device__ __nv_bfloat16  g_hlo[(size_t)TT * BB * HH];       // 128 MB

// ---------------- PTX helpers (all baseline: sm_80+) ----------------
__device__ __forceinline__ uint32_t smem_u32(const void* p) {
    uint32_t a;
    asm("{ .reg .u64 t; cvta.to.shared.u64 t, %1; cvt.u32.u64 %0, t; }" : "=r"(a) : "l"(p));
    return a;
}
__device__ __forceinline__ void ldsm4(uint32_t* r, uint32_t addr) {
    asm volatile("ldmatrix.sync.aligned.m8n8.x4.shared.b16 {%0,%1,%2,%3}, [%4];"
                 : "=r"(r[0]), "=r"(r[1]), "=r"(r[2]), "=r"(r[3]) : "r"(addr));
}
__device__ __forceinline__ void mma16816(float* d, const uint32_t* a, const uint32_t* b) {
    asm volatile("mma.sync.aligned.m16n8k16.row.col.f32.bf16.bf16.f32 "
                 "{%0,%1,%2,%3}, {%4,%5,%6,%7}, {%8,%9}, {%0,%1,%2,%3};"
                 : "+f"(d[0]), "+f"(d[1]), "+f"(d[2]), "+f"(d[3])
                 : "r"(a[0]), "r"(a[1]), "r"(a[2]), "r"(a[3]), "r"(b[0]), "r"(b[1]));
}
__device__ __forceinline__ void cpasync16(uint32_t saddr, const void* g) {
    asm volatile("cp.async.cg.shared.global [%0], [%1], 16;" :: "r"(saddr), "l"(g));
}
#define CP_COMMIT() asm volatile("cp.async.commit_group;")
#define CP_WAIT0()  asm volatile("cp.async.wait_group 0;")

__device__ __forceinline__ float sigm_f(float x) {
    x = fminf(fmaxf(x, -30.f), 30.f);
    return 1.f / (1.f + __expf(-x));
}
__device__ __forceinline__ float tanh_f(float x) {
    x = fminf(fmaxf(x, -15.f), 15.f);
    float e = __expf(2.f * x);
    return (e - 1.f) / (e + 1.f);
}

// ---------------- kernel: split+permute W_hh into bf16 hi/lo ----------------
__global__ void wsplit_kernel(const float* __restrict__ Whh) {
    int i = blockIdx.x * 256 + threadIdx.x;   // 2048*512 = 1M
    int j = i >> 9, k = i & 511;
    float w = Whh[i];
    int np = ((j & 511) << 2) + (j >> 9);     // gate-interleaved row: unit*4+gate
    __nv_bfloat16 hi = __float2bfloat16(w);
    g_whi[(size_t)np * HH + k] = hi;
    g_wlo[(size_t)np * HH + k] = __float2bfloat16(w - __bfloat162float(hi));
}

// ---------------- kernel: x_proj ([b][col'], gate-interleaved cols) ----------------
__global__ void xproj_kernel(const float* __restrict__ z,
                             const float* __restrict__ Wih,
                             const float* __restrict__ bih,
                             const float* __restrict__ bhh) {
    __shared__ float zs[16][68];
    __shared__ float ws[64][65];
    __shared__ float bs[64];
    int tid = threadIdx.x;
    int j0 = blockIdx.x * 64;
    int b0 = blockIdx.y * 16;

    for (int e = tid; e < 16 * 64; e += 256) {
        int r = e >> 6, c = e & 63;
        zs[r][c] = z[(b0 + r) * ZZ + c];
    }
    for (int e = tid; e < 64 * 64; e += 256) {
        int r = e >> 6, c = e & 63;
        ws[r][c] = Wih[(j0 + r) * (AA + ZZ) + AA + c];
    }
    if (tid < 64) bs[tid] = bih[j0 + tid] + bhh[j0 + tid];
    __syncthreads();

    int jl = tid & 63;
    int bq = tid >> 6;
    float acc[4];
#pragma unroll
    for (int bi = 0; bi < 4; bi++) acc[bi] = bs[jl];
#pragma unroll 8
    for (int k = 0; k < 64; k++) {
        float w = ws[jl][k];
#pragma unroll
        for (int bi = 0; bi < 4; bi++)
            acc[bi] = fmaf(zs[bq * 4 + bi][k], w, acc[bi]);
    }
    int jg = j0 + jl;
    int dest = ((jg & 511) << 2) + (jg >> 9);
#pragma unroll
    for (int bi = 0; bi < 4; bi++)
        g_xproj[(size_t)(b0 + bq * 4 + bi) * N4H + dest] = acc[bi];
}

// ---------------- step kernel: mma.sync split-bf16 GEMM + LSTM cell ----------------
// grid (16, 16): blockIdx.x = N tile (128 gate cols = 32 units), blockIdx.y = M tile (128 batch)
// occ 2. Per chunk: acc += hhi*whi + hhi*wlo + hlo*whi. ONE sync per chunk.
// Co-resident CTAs walk the K-chunks in rotated order (phase 0 / 8) so their
// ldsm bursts and barriers decorrelate (accumulation order change only).
__global__ __launch_bounds__(256, 2) void step_kernel(int t) {
    extern __shared__ __align__(16) char dsm[];

    const int tid = threadIdx.x, wid = tid >> 5, lid = tid & 31;
    const int warp_m = wid & 1, warp_n = wid >> 1;      // 2 x 4 warp grid, warp tile 64x32
    const int n0 = blockIdx.x * BN;
    const int b0 = blockIdx.y * BM;
    const int phase = ((blockIdx.x ^ blockIdx.y) & 1) * 8;
    const uint32_t sb = smem_u32(dsm);

    float acc[4][4][4];
#pragma unroll
    for (int mf = 0; mf < 4; mf++)
#pragma unroll
        for (int nf = 0; nf < 4; nf++)
#pragma unroll
            for (int j = 0; j < 4; j++) acc[mf][nf][j] = 0.f;

    if (t > 0) {
        const int r4  = tid >> 2, c4 = tid & 3;         // rows 0..63, 16B-col 0..3
        const int r4b = r4 + 64;                        // rows 64..127

        auto load_chunk = [&](int kc, int s) {
            int kk = kc * BK;
            const __nv_bfloat16* hh = g_hhi + ((size_t)(t - 1) * BB + b0) * HH + kk;
            const __nv_bfloat16* hl = g_hlo + ((size_t)(t - 1) * BB + b0) * HH + kk;
            const __nv_bfloat16* bw = g_whi + (size_t)n0 * HH + kk;
            const __nv_bfloat16* bl = g_wlo + (size_t)n0 * HH + kk;
            uint32_t st = sb + s * STAGE_B;
            uint32_t o1 = (r4  * LDS_ROW + c4 * 8) * 2;
            uint32_t o2 = (r4b * LDS_ROW + c4 * 8) * 2;
            size_t g1 = (size_t)r4 * HH + c4 * 8;
            size_t g2 = (size_t)r4b * HH + c4 * 8;
            cpasync16(st + 0 * TILE_B + o1, hh + g1);
            cpasync16(st + 0 * TILE_B + o2, hh + g2);
            cpasync16(st + 1 * TILE_B + o1, hl + g1);
            cpasync16(st + 1 * TILE_B + o2, hl + g2);
            cpasync16(st + 2 * TILE_B + o1, bw + g1);
            cpasync16(st + 2 * TILE_B + o2, bw + g2);
            cpasync16(st + 3 * TILE_B + o1, bl + g1);
            cpasync16(st + 3 * TILE_B + o2, bl + g2);
        };

        // per-lane ldmatrix address components
        const int sub = lid >> 3, lrow = lid & 7;
        const int rowA = warp_m * 64 + (sub & 1) * 8 + lrow;   // + mf*16
        const int kcA  = (sub >> 1);                            // + ks*2
        const int rowB = warp_n * 32 + (sub >> 1) * 8 + lrow;   // + np*16
        const int kcB  = (sub & 1);                             // + ks*2

        load_chunk(phase, 0);
        CP_COMMIT();

        for (int it = 0; it < NIT; it++) {
            int s = it & 1;
            CP_WAIT0();                    // chunk it resident (this thread)
            __syncthreads();               // visible to all; stage s^1 free for reuse
            if (it + 1 < NIT) {
                load_chunk((it + 1 + phase) & 15, s ^ 1);  // overlaps with compute
                CP_COMMIT();
            }

            uint32_t hhb = sb + s * STAGE_B;
            uint32_t hlb = hhb + TILE_B;
            uint32_t bwb = hhb + 2 * TILE_B;
            uint32_t blb = hhb + 3 * TILE_B;
#pragma unroll
            for (int ks = 0; ks < 2; ks++) {
                uint32_t bfw[2][4], bfl[2][4];
#pragma unroll
                for (int np = 0; np < 2; np++) {
                    uint32_t off = ((rowB + np * 16) * LDS_ROW + (kcB + ks * 2) * 8) * 2;
                    ldsm4(bfw[np], bwb + off);
                    ldsm4(bfl[np], blb + off);
                }
                {   // h_hi x {W_hi, W_lo}
                    uint32_t afr[4][4];
#pragma unroll
                    for (int mf = 0; mf < 4; mf++)
                        ldsm4(afr[mf], hhb + ((rowA + mf * 16) * LDS_ROW + (kcA + ks * 2) * 8) * 2);
#pragma unroll
                    for (int mf = 0; mf < 4; mf++)
#pragma unroll
                        for (int nf = 0; nf < 4; nf++)
                            mma16816(acc[mf][nf], afr[mf], &bfw[nf >> 1][(nf & 1) * 2]);
#pragma unroll
                    for (int mf = 0; mf < 4; mf++)
#pragma unroll
                        for (int nf = 0; nf < 4; nf++)
                            mma16816(acc[mf][nf], afr[mf], &bfl[nf >> 1][(nf & 1) * 2]);
                }
                {   // h_lo x W_hi
                    uint32_t afr[4][4];
#pragma unroll
                    for (int mf = 0; mf < 4; mf++)
                        ldsm4(afr[mf], hlb + ((rowA + mf * 16) * LDS_ROW + (kcA + ks * 2) * 8) * 2);
#pragma unroll
                    for (int mf = 0; mf < 4; mf++)
#pragma unroll
                        for (int nf = 0; nf < 4; nf++)
                            mma16816(acc[mf][nf], afr[mf], &bfw[nf >> 1][(nf & 1) * 2]);
                }
            }
        }
        __syncthreads();                   // last compute done before epilogue smem reuse
    }

    // ---- epilogue: gates -> LSTM cell, stage h(hi/lo) + c, coalesced writeback ----
    float*          stc  = (float*)dsm;                        // [128][33] fp32
    __nv_bfloat16*  sthi = (__nv_bfloat16*)(dsm + 16896);      // [128][34]
    __nv_bfloat16*  stlo = (__nv_bfloat16*)(dsm + 25600);      // [128][34]
    const int u0 = n0 >> 2;                                    // 32 units per tile

    const int q = lid & 3, g = lid >> 2;
    const bool even = (q & 1) == 0;

#pragma unroll
    for (int mf = 0; mf < 4; mf++) {
#pragma unroll
        for (int half = 0; half < 2; half++) {
            int r = warp_m * 64 + mf * 16 + g + half * 8;      // local batch row
            int b = b0 + r;
#pragma unroll
            for (int nf = 0; nf < 4; nf++) {
                int col = n0 + warp_n * 32 + nf * 8 + q * 2;   // global gate col (even)
                float v0 = acc[mf][nf][half * 2 + 0];
                float v1 = acc[mf][nf][half * 2 + 1];
                float2 xp = *(const float2*)&g_xproj[(size_t)b * N4H + col];
                v0 += xp.x; v1 += xp.y;
                // lane q holds cols (q*2, q*2+1); partner q^1 holds the other gate pair
                float w0 = __shfl_xor_sync(0xffffffffu, v0, 1);
                float w1 = __shfl_xor_sync(0xffffffffu, v1, 1);
                if (even) {
                    // this lane: (i, f); partner: (g, o)
                    float iv = sigm_f(v0);
                    float fv = sigm_f(v1);
                    float gv = tanh_f(w0);
                    float ov = sigm_f(w1);
                    int u = col >> 2;                          // global hidden unit
                    float cold = (t > 0) ? g_c[(size_t)b * HH + u] : 0.f;
                    float cn = fmaf(fv, cold, iv * gv);
                    float hn = ov * tanh_f(cn);
                    __nv_bfloat16 hi = __float2bfloat16(hn);
                    int ul = u - u0;
                    stc[r * 33 + ul]  = cn;
                    sthi[r * 34 + ul] = hi;
                    stlo[r * 34 + ul] = __float2bfloat16(hn - __bfloat162float(hi));
                }
            }
        }
    }
    __syncthreads();

    const size_t hb = ((size_t)t * BB + b0) * HH + u0;
#pragma unroll 4
    for (int idx = tid; idx < BM * 32; idx += 256) {
        int r = idx >> 5, u = idx & 31;
        g_c[(size_t)(b0 + r) * HH + u0 + u] = stc[r * 33 + u];
        g_hhi[hb + (size_t)r * HH + u] = sthi[r * 34 + u];
        g_hlo[hb + (size_t)r * HH + u] = stlo[r * 34 + u];
    }
}

// ---------------- output projection: out[b][t][a] = (hi+lo) . W_out[a] + b_out ----------------
__global__ __launch_bounds__(256) void out_kernel(const float* __restrict__ Wo,
                                                  const float* __restrict__ bo,
                                                  float* __restrict__ out) {
    __shared__ float Ws[AA * HH];
    for (int e = threadIdx.x; e < AA * HH; e += 256) Ws[e] = Wo[e];
    __syncthreads();

    int id = blockIdx.x * 256 + threadIdx.x;          // 131072 rows
    int tt = id >> 11;                                // t (0..63)
    int b = id & (BB - 1);
    const __nv_bfloat16* ph = g_hhi + ((size_t)tt * BB + b) * HH;
    const __nv_bfloat16* pl = g_hlo + ((size_t)tt * BB + b) * HH;

    float acc[AA];
#pragma unroll
    for (int a = 0; a < AA; a++) acc[a] = 0.f;

    for (int k = 0; k < HH; k += 8) {
        uint4 vh = *(const uint4*)(ph + k);
        uint4 vl = *(const uint4*)(pl + k);
        const __nv_bfloat162* h2 = (const __nv_bfloat162*)&vh;
        const __nv_bfloat162* l2 = (const __nv_bfloat162*)&vl;
        float hv[8];
#pragma unroll
        for (int m = 0; m < 4; m++) {
            float2 fh = __bfloat1622float2(h2[m]);
            float2 fl = __bfloat1622float2(l2[m]);
            hv[2 * m + 0] = fh.x + fl.x;
            hv[2 * m + 1] = fh.y + fl.y;
        }
#pragma unroll
        for (int a = 0; a < AA; a++) {
#pragma unroll
            for (int m = 0; m < 8; m++)
                acc[a] = fmaf(hv[m], Ws[a * HH + k + m], acc[a]);
        }
    }
#pragma unroll
    for (int a = 0; a < AA; a++)
        out[((size_t)b * TT + tt) * AA + a] = acc[a] + bo[a];
}

// ---------------- launch ----------------
extern "C" void kernel_launch(void* const* d_in, const int* in_sizes, int n_in,
                              void* d_out, int out_size) {
    const float* z    = (const float*)d_in[0];
    const float* Wih  = (const float*)d_in[1];
    const float* Whh  = (const float*)d_in[2];
    const float* bih  = (const float*)d_in[3];
    const float* bhh  = (const float*)d_in[4];
    const float* Wout = (const float*)d_in[5];
    const float* bout = (const float*)d_in[6];
    float* out = (float*)d_out;

    cudaFuncSetAttribute(step_kernel, cudaFuncAttributeMaxDynamicSharedMemorySize, DYN_SMEM);

    wsplit_kernel<<<(N4H * HH) / 256, 256>>>(Whh);
    xproj_kernel<<<dim3(N4H / 64, BB / 16), 256>>>(z, Wih, bih, bhh);
    for (int t = 0; t < TT; t++)
        step_kernel<<<dim3(N4H / BN, BB / BM), 256, DYN_SMEM>>>(t);
    out_kernel<<<(BB * TT) / 256, 256>>>(Wout, bout, out);
}